// round 2
// baseline (speedup 1.0000x reference)
#include <cuda_runtime.h>
#include <cfloat>

#define BB 8
#define NN 16384
#define SS 2048
#define DD 64
#define KNB 32
#define TN 128

// ---------------- device scratch (static, allocation-free) ----------------
__device__ float g_pnorm[BB * NN];                 // ||p||^2 per point
__device__ int   g_topk[BB * SS * KNB];            // top-32 neighbor indices
__device__ float g_h2[BB * NN * 128];              // per-point MLP output (64MB)
__device__ float g_w0f[64 * 64], g_w1f[64 * 64], g_w2f[128 * 64];
__device__ float g_b0f[64], g_b1f[64], g_b2f[128];

// fused 4-wide dot step: A/Bc are two partial-sum chains for ILP
#define DOT4STEP(wv, h0, h1, h2v, h3, A, Bc) \
    A  = fmaf((h0), (wv).x, A);  Bc = fmaf((h1), (wv).y, Bc); \
    A  = fmaf((h2v), (wv).z, A); Bc = fmaf((h3), (wv).w, Bc);

// ---------------- weight/BN folding ----------------
__global__ void k_prep(const float* __restrict__ w0, const float* __restrict__ b0,
                       const float* __restrict__ gg0, const float* __restrict__ be0,
                       const float* __restrict__ m0, const float* __restrict__ v0,
                       const float* __restrict__ w1, const float* __restrict__ b1,
                       const float* __restrict__ gg1, const float* __restrict__ be1,
                       const float* __restrict__ m1, const float* __restrict__ v1,
                       const float* __restrict__ w2, const float* __restrict__ b2,
                       const float* __restrict__ gg2, const float* __restrict__ be2,
                       const float* __restrict__ m2, const float* __restrict__ v2) {
    int o = threadIdx.x;  // 128 threads
    if (o < 64) {
        float s0 = gg0[o] * rsqrtf(v0[o] + 1e-5f);
        for (int c = 0; c < 64; c++) g_w0f[o * 64 + c] = w0[o * 64 + c] * s0;
        g_b0f[o] = (b0[o] - m0[o]) * s0 + be0[o];
        float s1 = gg1[o] * rsqrtf(v1[o] + 1e-5f);
        for (int c = 0; c < 64; c++) g_w1f[o * 64 + c] = w1[o * 64 + c] * s1;
        g_b1f[o] = (b1[o] - m1[o]) * s1 + be1[o];
    }
    float s2 = gg2[o] * rsqrtf(v2[o] + 1e-5f);
    for (int c = 0; c < 64; c++) g_w2f[o * 64 + c] = w2[o * 64 + c] * s2;
    g_b2f[o] = (b2[o] - m2[o]) * s2 + be2[o];
}

// ---------------- per-point squared norms ----------------
__global__ void k_pnorm(const float* __restrict__ points) {
    int i = blockIdx.x * blockDim.x + threadIdx.x;  // < B*N
    const float4* p = (const float4*)(points + (size_t)i * DD);
    float a0 = 0, a1 = 0, a2 = 0, a3 = 0;
#pragma unroll
    for (int u = 0; u < 16; u++) {
        float4 v = p[u];
        a0 = fmaf(v.x, v.x, a0); a1 = fmaf(v.y, v.y, a1);
        a2 = fmaf(v.z, v.z, a2); a3 = fmaf(v.w, v.w, a3);
    }
    g_pnorm[i] = (a0 + a1) + (a2 + a3);
}

// ---------------- new_xyz gather ----------------
__global__ void k_newxyz(const float* __restrict__ xyz, const int* __restrict__ sidx,
                         float* __restrict__ out) {
    int t = blockIdx.x * blockDim.x + threadIdx.x;
    if (t >= BB * SS * 3) return;
    int c = t % 3;
    int s = (t / 3) % SS;
    int b = t / (3 * SS);
    out[t] = xyz[((size_t)b * NN + sidx[s]) * 3 + c];
}

// ---------------- pointwise 3-layer MLP for all B*N points ----------------
// thread = point; h0 parked in per-thread smem column; h1 in registers.
__global__ void __launch_bounds__(128, 1) k_mlp(const float* __restrict__ points) {
    __shared__ float sh0[64 * 128];  // 32KB; reused as coalescing staging for layer2
    const int tid = threadIdx.x;
    const size_t pt = (size_t)blockIdx.x * 128 + tid;

    float4 x[16];
    {
        const float4* xp = (const float4*)(points + pt * DD);
#pragma unroll
        for (int u = 0; u < 16; u++) x[u] = xp[u];
    }

    // ---- layer 0: x(regs) -> sh0 (own column) ----
    for (int o4 = 0; o4 < 16; o4++) {
        const float4* wr0 = (const float4*)(g_w0f + (o4 * 4 + 0) * 64);
        const float4* wr1 = (const float4*)(g_w0f + (o4 * 4 + 1) * 64);
        const float4* wr2 = (const float4*)(g_w0f + (o4 * 4 + 2) * 64);
        const float4* wr3 = (const float4*)(g_w0f + (o4 * 4 + 3) * 64);
        float A0 = 0, A1 = 0, A2 = 0, A3 = 0, C0 = 0, C1 = 0, C2 = 0, C3 = 0;
#pragma unroll
        for (int u = 0; u < 16; u++) {
            float h0 = x[u].x, h1 = x[u].y, h2v = x[u].z, h3 = x[u].w;
            float4 w0v = wr0[u]; DOT4STEP(w0v, h0, h1, h2v, h3, A0, C0);
            float4 w1v = wr1[u]; DOT4STEP(w1v, h0, h1, h2v, h3, A1, C1);
            float4 w2v = wr2[u]; DOT4STEP(w2v, h0, h1, h2v, h3, A2, C2);
            float4 w3v = wr3[u]; DOT4STEP(w3v, h0, h1, h2v, h3, A3, C3);
        }
        sh0[(o4 * 4 + 0) * 128 + tid] = fmaxf(A0 + C0 + g_b0f[o4 * 4 + 0], 0.f);
        sh0[(o4 * 4 + 1) * 128 + tid] = fmaxf(A1 + C1 + g_b0f[o4 * 4 + 1], 0.f);
        sh0[(o4 * 4 + 2) * 128 + tid] = fmaxf(A2 + C2 + g_b0f[o4 * 4 + 2], 0.f);
        sh0[(o4 * 4 + 3) * 128 + tid] = fmaxf(A3 + C3 + g_b0f[o4 * 4 + 3], 0.f);
    }
    // no __syncthreads needed: each thread reads only its own column

    // ---- layer 1: sh0 -> h1 registers (fully unrolled so h1r stays in regs) ----
    float h1r[64];
#pragma unroll
    for (int o4 = 0; o4 < 16; o4++) {
        const float4* wr0 = (const float4*)(g_w1f + (o4 * 4 + 0) * 64);
        const float4* wr1 = (const float4*)(g_w1f + (o4 * 4 + 1) * 64);
        const float4* wr2 = (const float4*)(g_w1f + (o4 * 4 + 2) * 64);
        const float4* wr3 = (const float4*)(g_w1f + (o4 * 4 + 3) * 64);
        float A0 = 0, A1 = 0, A2 = 0, A3 = 0, C0 = 0, C1 = 0, C2 = 0, C3 = 0;
#pragma unroll
        for (int u = 0; u < 16; u++) {
            float h0 = sh0[(4 * u + 0) * 128 + tid];
            float h1 = sh0[(4 * u + 1) * 128 + tid];
            float h2v = sh0[(4 * u + 2) * 128 + tid];
            float h3 = sh0[(4 * u + 3) * 128 + tid];
            float4 w0v = wr0[u]; DOT4STEP(w0v, h0, h1, h2v, h3, A0, C0);
            float4 w1v = wr1[u]; DOT4STEP(w1v, h0, h1, h2v, h3, A1, C1);
            float4 w2v = wr2[u]; DOT4STEP(w2v, h0, h1, h2v, h3, A2, C2);
            float4 w3v = wr3[u]; DOT4STEP(w3v, h0, h1, h2v, h3, A3, C3);
        }
        h1r[o4 * 4 + 0] = fmaxf(A0 + C0 + g_b1f[o4 * 4 + 0], 0.f);
        h1r[o4 * 4 + 1] = fmaxf(A1 + C1 + g_b1f[o4 * 4 + 1], 0.f);
        h1r[o4 * 4 + 2] = fmaxf(A2 + C2 + g_b1f[o4 * 4 + 2], 0.f);
        h1r[o4 * 4 + 3] = fmaxf(A3 + C3 + g_b1f[o4 * 4 + 3], 0.f);
    }

    // ---- layer 2: h1r -> g_h2, staged through smem for coalesced stores ----
    float* stg = sh0;  // 32*129 floats needed <= 8192 available
    const size_t obase = (size_t)blockIdx.x * 128 * 128;
    for (int ch = 0; ch < 4; ch++) {
        __syncthreads();  // all threads done with sh0 reads / previous staging reads
        for (int o4 = 0; o4 < 8; o4++) {
            const int ob = ch * 32 + o4 * 4;
            const float4* wr0 = (const float4*)(g_w2f + (ob + 0) * 64);
            const float4* wr1 = (const float4*)(g_w2f + (ob + 1) * 64);
            const float4* wr2 = (const float4*)(g_w2f + (ob + 2) * 64);
            const float4* wr3 = (const float4*)(g_w2f + (ob + 3) * 64);
            float A0 = 0, A1 = 0, A2 = 0, A3 = 0, C0 = 0, C1 = 0, C2 = 0, C3 = 0;
#pragma unroll
            for (int u = 0; u < 16; u++) {
                float h0 = h1r[4 * u + 0], h1 = h1r[4 * u + 1];
                float h2v = h1r[4 * u + 2], h3 = h1r[4 * u + 3];
                float4 w0v = wr0[u]; DOT4STEP(w0v, h0, h1, h2v, h3, A0, C0);
                float4 w1v = wr1[u]; DOT4STEP(w1v, h0, h1, h2v, h3, A1, C1);
                float4 w2v = wr2[u]; DOT4STEP(w2v, h0, h1, h2v, h3, A2, C2);
                float4 w3v = wr3[u]; DOT4STEP(w3v, h0, h1, h2v, h3, A3, C3);
            }
            stg[(o4 * 4 + 0) * 129 + tid] = fmaxf(A0 + C0 + g_b2f[ob + 0], 0.f);
            stg[(o4 * 4 + 1) * 129 + tid] = fmaxf(A1 + C1 + g_b2f[ob + 1], 0.f);
            stg[(o4 * 4 + 2) * 129 + tid] = fmaxf(A2 + C2 + g_b2f[ob + 2], 0.f);
            stg[(o4 * 4 + 3) * 129 + tid] = fmaxf(A3 + C3 + g_b2f[ob + 3], 0.f);
        }
        __syncthreads();
        const int lane = tid & 31, grp = tid >> 5;
#pragma unroll 4
        for (int rr = grp; rr < 128; rr += 4) {
            g_h2[obase + (size_t)rr * 128 + ch * 32 + lane] = stg[lane * 129 + rr];
        }
    }
}

// ---------------- fused distance GEMM + running top-32 ----------------
// thread = sample (lane-indexed), q in registers, point tile in smem (broadcast reads).
__global__ void __launch_bounds__(128, 1) k_dist(const float* __restrict__ points,
                                                 const int* __restrict__ sidx) {
    extern __shared__ float dsm[];
    float* sP  = dsm;                 // TN*64
    float* sPn = sP + TN * 64;        // TN
    float* stv = sPn + TN;            // 128*33
    int*   sti = (int*)(stv + 128 * 33);

    const int tid = threadIdx.x;
    const int b = blockIdx.y;
    const int s = blockIdx.x * 128 + tid;

    // load query row (already scaled by 2 so score = pnorm - dot)
    float4 q[16];
    {
        const int qi = sidx[s];
        const float4* qp = (const float4*)(points + ((size_t)b * NN + qi) * DD);
#pragma unroll
        for (int u = 0; u < 16; u++) {
            float4 v = qp[u];
            v.x *= 2.f; v.y *= 2.f; v.z *= 2.f; v.w *= 2.f;
            q[u] = v;
        }
    }

#pragma unroll
    for (int j = 0; j < 32; j++) stv[tid * 33 + j] = FLT_MAX;
    float thr = FLT_MAX;
    int slot = 0;

    const float4* Pb = (const float4*)(points + (size_t)b * NN * DD);
    const float*  Pn = g_pnorm + b * NN;

    for (int t = 0; t < NN; t += TN) {
        __syncthreads();
        {
            float4* dst = (float4*)sP;
            const float4* src = Pb + (size_t)t * 16;
#pragma unroll
            for (int i = 0; i < 16; i++) dst[tid + i * 128] = src[tid + i * 128];
            if (tid < TN) sPn[tid] = Pn[t + tid];
        }
        __syncthreads();

#pragma unroll 2
        for (int p = 0; p < TN; p++) {
            const float4* pv = (const float4*)(sP + p * 64);
            float a0 = 0, a1 = 0, a2 = 0, a3 = 0;
#pragma unroll
            for (int u = 0; u < 16; u++) {
                float4 v = pv[u];
                a0 = fmaf(q[u].x, v.x, a0);
                a1 = fmaf(q[u].y, v.y, a1);
                a2 = fmaf(q[u].z, v.z, a2);
                a3 = fmaf(q[u].w, v.w, a3);
            }
            float sc = sPn[p] - ((a0 + a1) + (a2 + a3));
            if (sc < thr) {  // strict < keeps earlier index on exact ties (matches stable top_k)
                stv[tid * 33 + slot] = sc;
                sti[tid * 33 + slot] = t + p;
                float m = -FLT_MAX; int ms = 0;
#pragma unroll
                for (int j = 0; j < 32; j++) {
                    float vv = stv[tid * 33 + j];
                    if (vv > m) { m = vv; ms = j; }
                }
                thr = m; slot = ms;
            }
        }
    }

    int* op = g_topk + ((size_t)b * SS + s) * KNB;
#pragma unroll
    for (int j = 0; j < 32; j++) op[j] = sti[tid * 33 + j];
}

// ---------------- gather + channel max over the 32 neighbors ----------------
__global__ void k_gmax(float* __restrict__ out) {
    const int b = blockIdx.y, s = blockIdx.x, c = threadIdx.x;  // 128 threads
    __shared__ int si[32];
    if (threadIdx.x < 32) si[threadIdx.x] = g_topk[((size_t)b * SS + s) * KNB + threadIdx.x];
    __syncthreads();
    const float* hb = g_h2 + (size_t)b * NN * 128;
    float m = -FLT_MAX;
#pragma unroll 8
    for (int j = 0; j < 32; j++) m = fmaxf(m, hb[(size_t)si[j] * 128 + c]);
    out[((size_t)b * SS + s) * 128 + c] = m;
}

// ---------------- launch ----------------
extern "C" void kernel_launch(void* const* d_in, const int* in_sizes, int n_in,
                              void* d_out, int out_size) {
    const float* xyz    = (const float*)d_in[0];
    const float* points = (const float*)d_in[1];
    const int*   sidx   = (const int*)d_in[2];
    const float* w0 = (const float*)d_in[3];
    const float* b0 = (const float*)d_in[4];
    const float* gg0 = (const float*)d_in[5];
    const float* be0 = (const float*)d_in[6];
    const float* m0 = (const float*)d_in[7];
    const float* v0 = (const float*)d_in[8];
    const float* w1 = (const float*)d_in[9];
    const float* b1 = (const float*)d_in[10];
    const float* gg1 = (const float*)d_in[11];
    const float* be1 = (const float*)d_in[12];
    const float* m1 = (const float*)d_in[13];
    const float* v1 = (const float*)d_in[14];
    const float* w2 = (const float*)d_in[15];
    const float* b2 = (const float*)d_in[16];
    const float* gg2 = (const float*)d_in[17];
    const float* be2 = (const float*)d_in[18];
    const float* m2 = (const float*)d_in[19];
    const float* v2 = (const float*)d_in[20];

    float* out = (float*)d_out;
    float* out_xyz = nullptr;
    float* out_pts = out;
    if (out_size == BB * SS * 3 + BB * SS * 128) {
        out_xyz = out;
        out_pts = out + BB * SS * 3;
    }

    const int dist_smem = (TN * 64 + TN + 128 * 33 * 2) * 4;  // 67072 B
    cudaFuncSetAttribute(k_dist, cudaFuncAttributeMaxDynamicSharedMemorySize, dist_smem);

    k_prep<<<1, 128>>>(w0, b0, gg0, be0, m0, v0,
                       w1, b1, gg1, be1, m1, v1,
                       w2, b2, gg2, be2, m2, v2);
    k_pnorm<<<(BB * NN) / 256, 256>>>(points);
    if (out_xyz)
        k_newxyz<<<(BB * SS * 3 + 127) / 128, 128>>>(xyz, sidx, out_xyz);
    k_mlp<<<(BB * NN) / 128, 128>>>(points);
    k_dist<<<dim3(SS / 128, BB), 128, dist_smem>>>(points, sidx);
    k_gmax<<<dim3(SS, BB), 128>>>(out_pts);
}

// round 3
// speedup vs baseline: 1.0052x; 1.0052x over previous
#include <cuda_runtime.h>
#include <cfloat>

#define BB 8
#define NN 16384
#define SS 2048
#define DD 64
#define KNB 32
#define TN 128

// ---------------- device scratch (static, allocation-free) ----------------
__device__ float g_pnorm[BB * NN];                 // ||p||^2 per point
__device__ int   g_topk[BB * SS * KNB];            // top-32 neighbor indices
__device__ float g_h2[BB * NN * 128];              // per-point MLP output (64MB)
__device__ float g_w0f[64 * 64], g_w1f[64 * 64], g_w2f[128 * 64];
__device__ float g_b0f[64], g_b1f[64], g_b2f[128];

// fused 4-wide dot step: A/Bc are two partial-sum chains for ILP
#define DOT4STEP(wv, h0, h1, h2v, h3, A, Bc) \
    A  = fmaf((h0), (wv).x, A);  Bc = fmaf((h1), (wv).y, Bc); \
    A  = fmaf((h2v), (wv).z, A); Bc = fmaf((h3), (wv).w, Bc);

// ---------------- weight/BN folding ----------------
__global__ void k_prep(const float* __restrict__ w0, const float* __restrict__ b0,
                       const float* __restrict__ gg0, const float* __restrict__ be0,
                       const float* __restrict__ m0, const float* __restrict__ v0,
                       const float* __restrict__ w1, const float* __restrict__ b1,
                       const float* __restrict__ gg1, const float* __restrict__ be1,
                       const float* __restrict__ m1, const float* __restrict__ v1,
                       const float* __restrict__ w2, const float* __restrict__ b2,
                       const float* __restrict__ gg2, const float* __restrict__ be2,
                       const float* __restrict__ m2, const float* __restrict__ v2) {
    int o = threadIdx.x;  // 128 threads
    if (o < 64) {
        float s0 = gg0[o] * rsqrtf(v0[o] + 1e-5f);
        for (int c = 0; c < 64; c++) g_w0f[o * 64 + c] = w0[o * 64 + c] * s0;
        g_b0f[o] = (b0[o] - m0[o]) * s0 + be0[o];
        float s1 = gg1[o] * rsqrtf(v1[o] + 1e-5f);
        for (int c = 0; c < 64; c++) g_w1f[o * 64 + c] = w1[o * 64 + c] * s1;
        g_b1f[o] = (b1[o] - m1[o]) * s1 + be1[o];
    }
    float s2 = gg2[o] * rsqrtf(v2[o] + 1e-5f);
    for (int c = 0; c < 64; c++) g_w2f[o * 64 + c] = w2[o * 64 + c] * s2;
    g_b2f[o] = (b2[o] - m2[o]) * s2 + be2[o];
}

// ---------------- per-point squared norms ----------------
__global__ void k_pnorm(const float* __restrict__ points) {
    int i = blockIdx.x * blockDim.x + threadIdx.x;  // < B*N
    const float4* p = (const float4*)(points + (size_t)i * DD);
    float a0 = 0, a1 = 0, a2 = 0, a3 = 0;
#pragma unroll
    for (int u = 0; u < 16; u++) {
        float4 v = p[u];
        a0 = fmaf(v.x, v.x, a0); a1 = fmaf(v.y, v.y, a1);
        a2 = fmaf(v.z, v.z, a2); a3 = fmaf(v.w, v.w, a3);
    }
    g_pnorm[i] = (a0 + a1) + (a2 + a3);
}

// ---------------- new_xyz gather ----------------
__global__ void k_newxyz(const float* __restrict__ xyz, const int* __restrict__ sidx,
                         float* __restrict__ out) {
    int t = blockIdx.x * blockDim.x + threadIdx.x;
    if (t >= BB * SS * 3) return;
    int c = t % 3;
    int s = (t / 3) % SS;
    int b = t / (3 * SS);
    out[t] = xyz[((size_t)b * NN + sidx[s]) * 3 + c];
}

// ---------------- pointwise 3-layer MLP for all B*N points ----------------
// thread = point; h0 parked in per-thread smem column; h1 in registers.
__global__ void __launch_bounds__(128, 1) k_mlp(const float* __restrict__ points) {
    __shared__ float sh0[64 * 128];  // 32KB; reused as coalescing staging for layer2
    const int tid = threadIdx.x;
    const size_t pt = (size_t)blockIdx.x * 128 + tid;

    float4 x[16];
    {
        const float4* xp = (const float4*)(points + pt * DD);
#pragma unroll
        for (int u = 0; u < 16; u++) x[u] = xp[u];
    }

    // ---- layer 0: x(regs) -> sh0 (own column) ----
    for (int o4 = 0; o4 < 16; o4++) {
        const float4* wr0 = (const float4*)(g_w0f + (o4 * 4 + 0) * 64);
        const float4* wr1 = (const float4*)(g_w0f + (o4 * 4 + 1) * 64);
        const float4* wr2 = (const float4*)(g_w0f + (o4 * 4 + 2) * 64);
        const float4* wr3 = (const float4*)(g_w0f + (o4 * 4 + 3) * 64);
        float A0 = 0, A1 = 0, A2 = 0, A3 = 0, C0 = 0, C1 = 0, C2 = 0, C3 = 0;
#pragma unroll
        for (int u = 0; u < 16; u++) {
            float h0 = x[u].x, h1 = x[u].y, h2v = x[u].z, h3 = x[u].w;
            float4 w0v = wr0[u]; DOT4STEP(w0v, h0, h1, h2v, h3, A0, C0);
            float4 w1v = wr1[u]; DOT4STEP(w1v, h0, h1, h2v, h3, A1, C1);
            float4 w2v = wr2[u]; DOT4STEP(w2v, h0, h1, h2v, h3, A2, C2);
            float4 w3v = wr3[u]; DOT4STEP(w3v, h0, h1, h2v, h3, A3, C3);
        }
        sh0[(o4 * 4 + 0) * 128 + tid] = fmaxf(A0 + C0 + g_b0f[o4 * 4 + 0], 0.f);
        sh0[(o4 * 4 + 1) * 128 + tid] = fmaxf(A1 + C1 + g_b0f[o4 * 4 + 1], 0.f);
        sh0[(o4 * 4 + 2) * 128 + tid] = fmaxf(A2 + C2 + g_b0f[o4 * 4 + 2], 0.f);
        sh0[(o4 * 4 + 3) * 128 + tid] = fmaxf(A3 + C3 + g_b0f[o4 * 4 + 3], 0.f);
    }
    // no __syncthreads needed: each thread reads only its own column

    // ---- layer 1: sh0 -> h1 registers (fully unrolled so h1r stays in regs) ----
    float h1r[64];
#pragma unroll
    for (int o4 = 0; o4 < 16; o4++) {
        const float4* wr0 = (const float4*)(g_w1f + (o4 * 4 + 0) * 64);
        const float4* wr1 = (const float4*)(g_w1f + (o4 * 4 + 1) * 64);
        const float4* wr2 = (const float4*)(g_w1f + (o4 * 4 + 2) * 64);
        const float4* wr3 = (const float4*)(g_w1f + (o4 * 4 + 3) * 64);
        float A0 = 0, A1 = 0, A2 = 0, A3 = 0, C0 = 0, C1 = 0, C2 = 0, C3 = 0;
#pragma unroll
        for (int u = 0; u < 16; u++) {
            float h0 = sh0[(4 * u + 0) * 128 + tid];
            float h1 = sh0[(4 * u + 1) * 128 + tid];
            float h2v = sh0[(4 * u + 2) * 128 + tid];
            float h3 = sh0[(4 * u + 3) * 128 + tid];
            float4 w0v = wr0[u]; DOT4STEP(w0v, h0, h1, h2v, h3, A0, C0);
            float4 w1v = wr1[u]; DOT4STEP(w1v, h0, h1, h2v, h3, A1, C1);
            float4 w2v = wr2[u]; DOT4STEP(w2v, h0, h1, h2v, h3, A2, C2);
            float4 w3v = wr3[u]; DOT4STEP(w3v, h0, h1, h2v, h3, A3, C3);
        }
        h1r[o4 * 4 + 0] = fmaxf(A0 + C0 + g_b1f[o4 * 4 + 0], 0.f);
        h1r[o4 * 4 + 1] = fmaxf(A1 + C1 + g_b1f[o4 * 4 + 1], 0.f);
        h1r[o4 * 4 + 2] = fmaxf(A2 + C2 + g_b1f[o4 * 4 + 2], 0.f);
        h1r[o4 * 4 + 3] = fmaxf(A3 + C3 + g_b1f[o4 * 4 + 3], 0.f);
    }

    // ---- layer 2: h1r -> g_h2, staged through smem for coalesced stores ----
    float* stg = sh0;  // 32*129 floats needed <= 8192 available
    const size_t obase = (size_t)blockIdx.x * 128 * 128;
    for (int ch = 0; ch < 4; ch++) {
        __syncthreads();  // all threads done with sh0 reads / previous staging reads
        for (int o4 = 0; o4 < 8; o4++) {
            const int ob = ch * 32 + o4 * 4;
            const float4* wr0 = (const float4*)(g_w2f + (ob + 0) * 64);
            const float4* wr1 = (const float4*)(g_w2f + (ob + 1) * 64);
            const float4* wr2 = (const float4*)(g_w2f + (ob + 2) * 64);
            const float4* wr3 = (const float4*)(g_w2f + (ob + 3) * 64);
            float A0 = 0, A1 = 0, A2 = 0, A3 = 0, C0 = 0, C1 = 0, C2 = 0, C3 = 0;
#pragma unroll
            for (int u = 0; u < 16; u++) {
                float h0 = h1r[4 * u + 0], h1 = h1r[4 * u + 1];
                float h2v = h1r[4 * u + 2], h3 = h1r[4 * u + 3];
                float4 w0v = wr0[u]; DOT4STEP(w0v, h0, h1, h2v, h3, A0, C0);
                float4 w1v = wr1[u]; DOT4STEP(w1v, h0, h1, h2v, h3, A1, C1);
                float4 w2v = wr2[u]; DOT4STEP(w2v, h0, h1, h2v, h3, A2, C2);
                float4 w3v = wr3[u]; DOT4STEP(w3v, h0, h1, h2v, h3, A3, C3);
            }
            stg[(o4 * 4 + 0) * 129 + tid] = fmaxf(A0 + C0 + g_b2f[ob + 0], 0.f);
            stg[(o4 * 4 + 1) * 129 + tid] = fmaxf(A1 + C1 + g_b2f[ob + 1], 0.f);
            stg[(o4 * 4 + 2) * 129 + tid] = fmaxf(A2 + C2 + g_b2f[ob + 2], 0.f);
            stg[(o4 * 4 + 3) * 129 + tid] = fmaxf(A3 + C3 + g_b2f[ob + 3], 0.f);
        }
        __syncthreads();
        const int lane = tid & 31, grp = tid >> 5;
#pragma unroll 4
        for (int rr = grp; rr < 128; rr += 4) {
            g_h2[obase + (size_t)rr * 128 + ch * 32 + lane] = stg[lane * 129 + rr];
        }
    }
}

// ---------------- fused distance GEMM + running top-32 ----------------
// thread = sample (lane-indexed), q in registers, point tile in smem (broadcast reads).
__global__ void __launch_bounds__(128, 1) k_dist(const float* __restrict__ points,
                                                 const int* __restrict__ sidx) {
    extern __shared__ float dsm[];
    float* sP  = dsm;                 // TN*64
    float* sPn = sP + TN * 64;        // TN
    float* stv = sPn + TN;            // 128*33
    int*   sti = (int*)(stv + 128 * 33);

    const int tid = threadIdx.x;
    const int b = blockIdx.y;
    const int s = blockIdx.x * 128 + tid;

    // load query row (already scaled by 2 so score = pnorm - dot)
    float4 q[16];
    {
        const int qi = sidx[s];
        const float4* qp = (const float4*)(points + ((size_t)b * NN + qi) * DD);
#pragma unroll
        for (int u = 0; u < 16; u++) {
            float4 v = qp[u];
            v.x *= 2.f; v.y *= 2.f; v.z *= 2.f; v.w *= 2.f;
            q[u] = v;
        }
    }

#pragma unroll
    for (int j = 0; j < 32; j++) stv[tid * 33 + j] = FLT_MAX;
    float thr = FLT_MAX;
    int slot = 0;

    const float4* Pb = (const float4*)(points + (size_t)b * NN * DD);
    const float*  Pn = g_pnorm + b * NN;

    for (int t = 0; t < NN; t += TN) {
        __syncthreads();
        {
            float4* dst = (float4*)sP;
            const float4* src = Pb + (size_t)t * 16;
#pragma unroll
            for (int i = 0; i < 16; i++) dst[tid + i * 128] = src[tid + i * 128];
            if (tid < TN) sPn[tid] = Pn[t + tid];
        }
        __syncthreads();

#pragma unroll 2
        for (int p = 0; p < TN; p++) {
            const float4* pv = (const float4*)(sP + p * 64);
            float a0 = 0, a1 = 0, a2 = 0, a3 = 0;
#pragma unroll
            for (int u = 0; u < 16; u++) {
                float4 v = pv[u];
                a0 = fmaf(q[u].x, v.x, a0);
                a1 = fmaf(q[u].y, v.y, a1);
                a2 = fmaf(q[u].z, v.z, a2);
                a3 = fmaf(q[u].w, v.w, a3);
            }
            float sc = sPn[p] - ((a0 + a1) + (a2 + a3));
            if (sc < thr) {  // strict < keeps earlier index on exact ties (matches stable top_k)
                stv[tid * 33 + slot] = sc;
                sti[tid * 33 + slot] = t + p;
                float m = -FLT_MAX; int ms = 0;
#pragma unroll
                for (int j = 0; j < 32; j++) {
                    float vv = stv[tid * 33 + j];
                    if (vv > m) { m = vv; ms = j; }
                }
                thr = m; slot = ms;
            }
        }
    }

    int* op = g_topk + ((size_t)b * SS + s) * KNB;
#pragma unroll
    for (int j = 0; j < 32; j++) op[j] = sti[tid * 33 + j];
}

// ---------------- gather + channel max over the 32 neighbors ----------------
__global__ void k_gmax(float* __restrict__ out) {
    const int b = blockIdx.y, s = blockIdx.x, c = threadIdx.x;  // 128 threads
    __shared__ int si[32];
    if (threadIdx.x < 32) si[threadIdx.x] = g_topk[((size_t)b * SS + s) * KNB + threadIdx.x];
    __syncthreads();
    const float* hb = g_h2 + (size_t)b * NN * 128;
    float m = -FLT_MAX;
#pragma unroll 8
    for (int j = 0; j < 32; j++) m = fmaxf(m, hb[(size_t)si[j] * 128 + c]);
    out[((size_t)b * SS + s) * 128 + c] = m;
}

// ---------------- launch ----------------
extern "C" void kernel_launch(void* const* d_in, const int* in_sizes, int n_in,
                              void* d_out, int out_size) {
    const float* xyz    = (const float*)d_in[0];
    const float* points = (const float*)d_in[1];
    const int*   sidx   = (const int*)d_in[2];
    const float* w0 = (const float*)d_in[3];
    const float* b0 = (const float*)d_in[4];
    const float* gg0 = (const float*)d_in[5];
    const float* be0 = (const float*)d_in[6];
    const float* m0 = (const float*)d_in[7];
    const float* v0 = (const float*)d_in[8];
    const float* w1 = (const float*)d_in[9];
    const float* b1 = (const float*)d_in[10];
    const float* gg1 = (const float*)d_in[11];
    const float* be1 = (const float*)d_in[12];
    const float* m1 = (const float*)d_in[13];
    const float* v1 = (const float*)d_in[14];
    const float* w2 = (const float*)d_in[15];
    const float* b2 = (const float*)d_in[16];
    const float* gg2 = (const float*)d_in[17];
    const float* be2 = (const float*)d_in[18];
    const float* m2 = (const float*)d_in[19];
    const float* v2 = (const float*)d_in[20];

    float* out = (float*)d_out;
    float* out_xyz = nullptr;
    float* out_pts = out;
    if (out_size == BB * SS * 3 + BB * SS * 128) {
        out_xyz = out;
        out_pts = out + BB * SS * 3;
    }

    const int dist_smem = (TN * 64 + TN + 128 * 33 * 2) * 4;  // 67072 B
    cudaFuncSetAttribute(k_dist, cudaFuncAttributeMaxDynamicSharedMemorySize, dist_smem);

    k_prep<<<1, 128>>>(w0, b0, gg0, be0, m0, v0,
                       w1, b1, gg1, be1, m1, v1,
                       w2, b2, gg2, be2, m2, v2);
    k_pnorm<<<(BB * NN) / 256, 256>>>(points);
    if (out_xyz)
        k_newxyz<<<(BB * SS * 3 + 127) / 128, 128>>>(xyz, sidx, out_xyz);
    k_mlp<<<(BB * NN) / 128, 128>>>(points);
    k_dist<<<dim3(SS / 128, BB), 128, dist_smem>>>(points, sidx);
    k_gmax<<<dim3(SS, BB), 128>>>(out_pts);
}